// round 2
// baseline (speedup 1.0000x reference)
#include <cuda_runtime.h>
#include <math.h>
#include <float.h>

#define BB 8
#define CC 64
#define HH 62
#define TT 400
#define HT (HH*TT)            // 24800
#define NTOT (BB*CC*HT)       // 12697600
#define SSZ 32
#define MIDC 4

// ---------------- scratch (device globals; no allocation allowed) ----------------
__device__ float g_A[NTOT];   // h / half2 output (un-reversed)
__device__ float g_B2[NTOT];  // b1
__device__ float g_C2[NTOT];  // b2
__device__ float g_D2[NTOT];  // cb
__device__ float g_E2[NTOT];  // half1 output
__device__ float g_avg[BB*CC], g_mxv[BB*CC], g_ach[BB*CC];
__device__ float g_sp[BB*2*HT];
__device__ float g_asp[BB*HT];
__device__ float g_sc[TT*CC];

// ---------------- pointwise 64x64 channel mix (+optional bn, act) ----------------
// ACT: 0=none, 1=relu, 2=sigmoid. In-place safe (tile loaded fully before writes).
template<int ACT>
__global__ void pw_kernel(const float* __restrict__ in, const float* __restrict__ W,
                          const float* __restrict__ gamma, const float* __restrict__ beta,
                          float* __restrict__ out)
{
    __shared__ float sW[CC*CC];
    __shared__ float sx[CC][64];
    int b  = blockIdx.y;
    int tx = threadIdx.x, ty = threadIdx.y;
    int tid = ty*64 + tx;
    #pragma unroll
    for (int i = 0; i < 16; i++) sW[i*256 + tid] = W[i*256 + tid];
    int pos = blockIdx.x*64 + tx;
    bool ok = pos < HT;
    const float* inb = in + (size_t)b*CC*HT;
    #pragma unroll
    for (int i = 0; i < 16; i++) {
        int c = ty*16 + i;
        sx[c][tx] = ok ? inb[(size_t)c*HT + pos] : 0.f;
    }
    __syncthreads();
    if (!ok) return;
    float* outb = out + (size_t)b*CC*HT;
    #pragma unroll
    for (int i = 0; i < 16; i++) {
        int o = ty*16 + i;
        float acc = 0.f;
        #pragma unroll
        for (int c = 0; c < CC; c++) acc = fmaf(sW[o*CC + c], sx[c][tx], acc);
        if (gamma) acc = acc*gamma[o] + beta[o];
        if (ACT == 1) acc = fmaxf(acc, 0.f);
        if (ACT == 2) acc = 1.f/(1.f + expf(-acc));
        outb[(size_t)o*HT + pos] = acc;
    }
}

// ---------------- dual depthwise 5x5 conv, pad 2, optional reversed-T read -------
__global__ void dw5_dual(const float* __restrict__ in, const float* __restrict__ w0,
                         const float* __restrict__ w1,
                         float* __restrict__ out0, float* __restrict__ out1, int rev)
{
    int bc = blockIdx.z;
    int c  = bc & (CC-1);
    __shared__ float tile[12][36];
    int t0 = blockIdx.x*32 - 2;
    int h0 = blockIdx.y*8  - 2;
    const float* base = in + (size_t)bc*HT;
    int tid = threadIdx.y*32 + threadIdx.x;
    for (int i = tid; i < 12*36; i += 256) {
        int hh = i / 36, tt = i % 36;
        int h = h0 + hh, t = t0 + tt;
        float v = 0.f;
        if (h >= 0 && h < HH && t >= 0 && t < TT) {
            int tr = rev ? (TT-1-t) : t;
            v = base[h*TT + tr];
        }
        tile[hh][tt] = v;
    }
    __syncthreads();
    int t = blockIdx.x*32 + threadIdx.x;
    int h = blockIdx.y*8  + threadIdx.y;
    if (t >= TT || h >= HH) return;
    const float* W0 = w0 + c*25;
    const float* W1 = w1 + c*25;
    float a0 = 0.f, a1 = 0.f;
    #pragma unroll
    for (int kh = 0; kh < 5; kh++)
        #pragma unroll
        for (int kw = 0; kw < 5; kw++) {
            float v = tile[threadIdx.y+kh][threadIdx.x+kw];
            a0 = fmaf(v, __ldg(&W0[kh*5+kw]), a0);
            a1 = fmaf(v, __ldg(&W1[kh*5+kw]), a1);
        }
    out0[(size_t)bc*HT + h*TT + t] = a0;
    out1[(size_t)bc*HT + h*TT + t] = a1;
}

// ---------------- channel attention: per-(b,c) mean & max over HxT ---------------
__global__ void chan_stats(const float* __restrict__ in, float* __restrict__ avg,
                           float* __restrict__ mx)
{
    int bc = blockIdx.x;
    const float* p = in + (size_t)bc*HT;
    float s = 0.f, m = -FLT_MAX;
    for (int i = threadIdx.x; i < HT; i += 256) { float v = p[i]; s += v; m = fmaxf(m, v); }
    __shared__ float ssm[256], smm[256];
    ssm[threadIdx.x] = s; smm[threadIdx.x] = m;
    __syncthreads();
    for (int st = 128; st > 0; st >>= 1) {
        if (threadIdx.x < st) {
            ssm[threadIdx.x] += ssm[threadIdx.x+st];
            smm[threadIdx.x] = fmaxf(smm[threadIdx.x], smm[threadIdx.x+st]);
        }
        __syncthreads();
    }
    if (threadIdx.x == 0) { avg[bc] = ssm[0]/(float)HT; mx[bc] = smm[0]; }
}

// ---------------- channel attention MLP: a[b,c] = sigmoid(fc(avg)+fc(max)) ------
__global__ void chan_attn(const float* __restrict__ avg, const float* __restrict__ mx,
                          const float* __restrict__ w1, const float* __restrict__ w2,
                          float* __restrict__ a)
{
    int b = blockIdx.x;
    int c = threadIdx.x;   // 64 threads
    __shared__ float sa[CC], sm[CC], hs[MIDC];
    sa[c] = avg[b*CC + c];
    sm[c] = mx[b*CC + c];
    __syncthreads();
    if (c < MIDC) {
        float ha = 0.f, hm = 0.f;
        for (int k = 0; k < CC; k++) {
            ha = fmaf(sa[k], w1[c*CC + k], ha);
            hm = fmaf(sm[k], w1[c*CC + k], hm);
        }
        hs[c] = fmaxf(ha, 0.f) + fmaxf(hm, 0.f);
    }
    __syncthreads();
    float acc = 0.f;
    #pragma unroll
    for (int j = 0; j < MIDC; j++) acc = fmaf(hs[j], w2[c*MIDC + j], acc);
    a[b*CC + c] = 1.f/(1.f + expf(-acc));
}

// ---------------- 1x3 depthwise conv along T on (b1^2 * a_ch), pad 1 ------------
__global__ void dw1x3_kernel(const float* __restrict__ b1, const float* __restrict__ ach,
                             const float* __restrict__ w, float* __restrict__ out)
{
    long long idx = (long long)blockIdx.x*blockDim.x + threadIdx.x;
    if (idx >= NTOT) return;
    int t = (int)(idx % TT);
    long long row = idx - t;
    int bc = (int)(idx / HT);
    int c = bc & (CC-1), b = bc >> 6;
    float a = ach[b*CC + c];
    const float* p = b1 + row;
    float w0 = w[c*3+0], w1 = w[c*3+1], w2 = w[c*3+2];
    float acc = 0.f;
    if (t > 0)    { float v = p[t-1]; acc = fmaf(w0, v*v*a, acc); }
    { float v = p[t];   acc = fmaf(w1, v*v*a, acc); }
    if (t < TT-1) { float v = p[t+1]; acc = fmaf(w2, v*v*a, acc); }
    out[idx] = acc;
}

// ---------------- spatial attention stats: mean/max over channels ---------------
__global__ void spat_stats(const float* __restrict__ b2, float* __restrict__ sp)
{
    int pos = blockIdx.x*256 + threadIdx.x;
    int b = blockIdx.y;
    if (pos >= HT) return;
    const float* p = b2 + (size_t)b*CC*HT + pos;
    float s = 0.f, m = -FLT_MAX;
    #pragma unroll 8
    for (int c = 0; c < CC; c++) { float v = p[(size_t)c*HT]; s += v; m = fmaxf(m, v); }
    sp[(size_t)b*2*HT + pos]      = s*(1.f/CC);
    sp[(size_t)b*2*HT + HT + pos] = m;
}

// ---------------- spatial attention 7x7 conv (2ch->1) + sigmoid -----------------
__global__ void spat_conv(const float* __restrict__ sp, const float* __restrict__ w,
                          float* __restrict__ asp)
{
    int t = blockIdx.x*32 + threadIdx.x;
    int h = blockIdx.y*8  + threadIdx.y;
    int b = blockIdx.z;
    if (t >= TT || h >= HH) return;
    float acc = 0.f;
    #pragma unroll
    for (int ci = 0; ci < 2; ci++) {
        const float* base = sp + ((size_t)b*2 + ci)*HT;
        #pragma unroll
        for (int kh = 0; kh < 7; kh++) {
            int hh = h + kh - 3;
            if (hh < 0 || hh >= HH) continue;
            #pragma unroll
            for (int kw = 0; kw < 7; kw++) {
                int tt = t + kw - 3;
                if (tt < 0 || tt >= TT) continue;
                acc = fmaf(base[hh*TT + tt], __ldg(&w[ci*49 + kh*7 + kw]), acc);
            }
        }
    }
    asp[(size_t)b*HT + h*TT + t] = 1.f/(1.f + expf(-acc));
}

// ---------------- SSM precompute: state is input-independent! -------------------
// state_t = state_{t-1} @ A.T + B (updated before emit), sc[t] = state_t @ C
__global__ void ssm_pre(const float* __restrict__ A, const float* __restrict__ Bv,
                        const float* __restrict__ Cm, float* __restrict__ sc)
{
    __shared__ float st[SSZ], nst[SSZ];
    int tid = threadIdx.x;   // 64 threads
    if (tid < SSZ) st[tid] = 0.f;
    __syncthreads();
    for (int t = 0; t < TT; t++) {
        if (tid < SSZ) {
            float acc = Bv[tid];
            #pragma unroll
            for (int j = 0; j < SSZ; j++) acc = fmaf(st[j], A[tid*SSZ + j], acc);
            nst[tid] = acc;
        }
        __syncthreads();
        if (tid < SSZ) st[tid] = nst[tid];
        __syncthreads();
        float acc = 0.f;
        #pragma unroll
        for (int i = 0; i < SSZ; i++) acc = fmaf(st[i], Cm[i*CC + tid], acc);
        sc[t*CC + tid] = acc;
    }
}

// ---------------- fused: residual-gelu + channel-LN + spatial gate --------------
// KEY: reference does x.reshape(b*h, c, t) which is a RAW reshape (C*T != H*T),
// so the scan-channel for true coords (c,h) is c2 = (62*c + h) mod 64 = (h-2c)&63.
// gelu term uses sc[t, c2], D[c2]; LayerNorm is over TRUE channels.
__global__ void final_fuse(const float* __restrict__ cb, const float* __restrict__ b2,
                           const float* __restrict__ asp, const float* __restrict__ sc,
                           const float* __restrict__ Dv, const float* __restrict__ lg,
                           const float* __restrict__ lb, float* __restrict__ out, int revout)
{
    int b = blockIdx.y;
    int pos = blockIdx.x*128 + threadIdx.x;
    if (pos >= HT) return;
    const float* cbb = cb + (size_t)b*CC*HT + pos;
    const float* b2b = b2 + (size_t)b*CC*HT + pos;
    int t = pos % TT, h = pos / TT;
    const float* scp = sc + t*CC;
    float v[CC];
    float sum = 0.f;
    #pragma unroll
    for (int c = 0; c < CC; c++) {
        int c2 = (h - 2*c) & (CC-1);      // scrambled scan-channel
        float x = cbb[(size_t)c*HT];
        float pre = scp[c2] + x*Dv[c2];
        float gel = 0.5f*pre*(1.f + erff(pre*0.70710678118654752f));
        float val = x + gel;
        v[c] = val; sum += val;
    }
    float mu = sum*(1.f/CC);
    float var = 0.f;
    #pragma unroll
    for (int c = 0; c < CC; c++) { float d = v[c]-mu; var = fmaf(d, d, var); }
    float rstd = rsqrtf(var*(1.f/CC) + 1e-5f);
    float aspv = asp[(size_t)b*HT + pos];
    int opos = revout ? (h*TT + (TT-1-t)) : pos;
    float* outb = out + (size_t)b*CC*HT + opos;
    #pragma unroll
    for (int c = 0; c < CC; c++) {
        float y = (v[c]-mu)*rstd*lg[c] + lb[c];
        float bv = b2b[(size_t)c*HT];
        float sb = 1.f/(1.f + expf(-(bv*bv*aspv)));
        outb[(size_t)c*HT] = y*sb;
    }
}

// ---------------- host-side orchestration ---------------------------------------
static void run_half(const float* in, float* outb, int rev,
                     const float* dwdw, const float* dwpw, const float* dwg, const float* dwb,
                     const float* caw1, const float* caw2, const float* saw,
                     const float* d1dw, const float* d1pw, const float* d1g, const float* d1b,
                     const float* sA, const float* sB, const float* sC, const float* sD,
                     const float* lng, const float* lnb,
                     float* bufB, float* bufC, float* bufD,
                     float* pavg, float* pmx, float* pach, float* psp, float* pasp, float* psc)
{
    dim3 g5((TT+31)/32, (HH+7)/8, BB*CC), b5(32, 8);
    dw5_dual<<<g5, b5>>>(in, dwdw, dwdw + CC*25, bufB, bufC, rev);

    dim3 gp((HT+63)/64, BB), bp(64, 4);
    pw_kernel<1><<<gp, bp>>>(bufB, dwpw,        dwg,     dwb,     bufB);   // b1
    pw_kernel<1><<<gp, bp>>>(bufC, dwpw+CC*CC,  dwg+CC,  dwb+CC,  bufC);   // b2

    chan_stats<<<BB*CC, 256>>>(bufB, pavg, pmx);
    chan_attn<<<BB, 64>>>(pavg, pmx, caw1, caw2, pach);

    dw1x3_kernel<<<(NTOT+255)/256, 256>>>(bufB, pach, d1dw, bufD);
    pw_kernel<2><<<gp, bp>>>(bufD, d1pw, d1g, d1b, bufD);                  // cb

    spat_stats<<<dim3((HT+255)/256, BB), 256>>>(bufC, psp);
    spat_conv<<<dim3((TT+31)/32, (HH+7)/8, BB), dim3(32, 8)>>>(psp, saw, pasp);

    ssm_pre<<<1, 64>>>(sA, sB, sC, psc);

    final_fuse<<<dim3((HT+127)/128, BB), 128>>>(bufD, bufC, pasp, psc, sD, lng, lnb, outb, rev);
}

extern "C" void kernel_launch(void* const* d_in, const int* in_sizes, int n_in,
                              void* d_out, int out_size)
{
    const float* x       = (const float*)d_in[0];
    const float* in_w    = (const float*)d_in[1];
    const float* dw2d_dw = (const float*)d_in[2];
    const float* dw2d_pw = (const float*)d_in[3];
    const float* dw2d_g  = (const float*)d_in[4];
    const float* dw2d_b  = (const float*)d_in[5];
    const float* ca_w1   = (const float*)d_in[6];
    const float* ca_w2   = (const float*)d_in[7];
    const float* sa_w    = (const float*)d_in[8];
    const float* dw1d_dw = (const float*)d_in[9];
    const float* dw1d_pw = (const float*)d_in[10];
    const float* dw1d_g  = (const float*)d_in[11];
    const float* dw1d_b  = (const float*)d_in[12];
    const float* ssm_A   = (const float*)d_in[13];
    const float* ssm_B   = (const float*)d_in[14];
    const float* ssm_C   = (const float*)d_in[15];
    const float* ssm_D   = (const float*)d_in[16];
    const float* ln_g    = (const float*)d_in[17];
    const float* ln_b    = (const float*)d_in[18];
    const float* out_w   = (const float*)d_in[19];
    const float* out_g   = (const float*)d_in[20];
    const float* out_b   = (const float*)d_in[21];

    float *pA, *pB, *pC, *pD, *pE, *pavg, *pmx, *pach, *psp, *pasp, *psc;
    cudaGetSymbolAddress((void**)&pA,   g_A);
    cudaGetSymbolAddress((void**)&pB,   g_B2);
    cudaGetSymbolAddress((void**)&pC,   g_C2);
    cudaGetSymbolAddress((void**)&pD,   g_D2);
    cudaGetSymbolAddress((void**)&pE,   g_E2);
    cudaGetSymbolAddress((void**)&pavg, g_avg);
    cudaGetSymbolAddress((void**)&pmx,  g_mxv);
    cudaGetSymbolAddress((void**)&pach, g_ach);
    cudaGetSymbolAddress((void**)&psp,  g_sp);
    cudaGetSymbolAddress((void**)&pasp, g_asp);
    cudaGetSymbolAddress((void**)&psc,  g_sc);

    dim3 gp((HT+63)/64, BB), bp(64, 4);

    // input pointwise mix
    pw_kernel<0><<<gp, bp>>>(x, in_w, nullptr, nullptr, pA);

    // half 1 (normal orientation)
    run_half(pA, pE, 0,
             dw2d_dw, dw2d_pw, dw2d_g, dw2d_b,
             ca_w1, ca_w2, sa_w,
             dw1d_dw, dw1d_pw, dw1d_g, dw1d_b,
             ssm_A, ssm_B, ssm_C, ssm_D, ln_g, ln_b,
             pB, pC, pD, pavg, pmx, pach, psp, pasp, psc);

    // half 2 (reversed read, reversed write-back)
    run_half(pE, pA, 1,
             dw2d_dw + 2*CC*25, dw2d_pw + 2*CC*CC, dw2d_g + 2*CC, dw2d_b + 2*CC,
             ca_w1 + MIDC*CC, ca_w2 + CC*MIDC, sa_w + 2*49,
             dw1d_dw + CC*3, dw1d_pw + CC*CC, dw1d_g + CC, dw1d_b + CC,
             ssm_A + SSZ*SSZ, ssm_B + SSZ, ssm_C + SSZ*CC, ssm_D + CC,
             ln_g + CC, ln_b + CC,
             pB, pC, pD, pavg, pmx, pach, psp, pasp, psc);

    // output pointwise mix + bn + relu
    pw_kernel<1><<<gp, bp>>>(pA, out_w, out_g, out_b, (float*)d_out);
}

// round 3
// speedup vs baseline: 1.9153x; 1.9153x over previous
#include <cuda_runtime.h>
#include <math.h>
#include <float.h>

#define BB 8
#define CC 64
#define HH 62
#define TT 400
#define HT (HH*TT)            // 24800
#define NTOT (BB*CC*HT)       // 12697600
#define SSZ 32
#define MIDC 4

// ---------------- scratch (device globals) ----------------
__device__ float g_A[NTOT];   // h / half2 output (un-reversed)
__device__ float g_B2[NTOT];  // b1
__device__ float g_C2[NTOT];  // b2
__device__ float g_D2[NTOT];  // cb
__device__ float g_E2[NTOT];  // half1 output
__device__ float g_avg[BB*CC], g_mxv[BB*CC], g_ach[BB*CC];
__device__ float g_sp[BB*2*HT];
__device__ float g_asp[BB*HT];
__device__ float g_sc[2*TT*CC];

// ============ register-blocked pointwise 64x64 channel mix =================
// Block: 256 threads = 32 pos-groups (4 pos each) x 8 out-groups (8 outs each).
// Tile: 128 positions. smem: sW 16KB @0, sx 32KB @16KB, [stats 8KB @48KB].
// ACT: 0=none, 1=relu, 2=sigmoid. In-place safe.
template<int ACT, bool SPSTATS>
__launch_bounds__(256)
__global__ void pw2(const float* __restrict__ in, const float* __restrict__ W,
                    const float* __restrict__ gamma, const float* __restrict__ beta,
                    float* __restrict__ out, float* __restrict__ sp)
{
    extern __shared__ float sm[];
    float* sW = sm;            // 4096 floats
    float* sx = sm + 4096;     // 64*128 floats
    float* sredS = sm + 4096 + 8192;         // 8*128 (SPSTATS)
    float* sredM = sredS + 1024;             // 8*128

    int tid = threadIdx.x;
    int px = tid & 31, oy = tid >> 5;
    int b = blockIdx.y;
    int pos0 = blockIdx.x * 128;
    const float* inb = in + (size_t)b*CC*HT;

    // load W
    #pragma unroll
    for (int i = tid; i < 1024; i += 256)
        ((float4*)sW)[i] = ((const float4*)W)[i];

    // load x tile [64 c][128 pos]
    #pragma unroll
    for (int i = tid; i < 2048; i += 256) {
        int c = i >> 5, j = i & 31;
        int gp = pos0 + j*4;
        float4 v = make_float4(0.f,0.f,0.f,0.f);
        if (gp + 3 < HT) {
            v = *(const float4*)(inb + (size_t)c*HT + gp);
        } else {
            float tmp[4] = {0,0,0,0};
            for (int k = 0; k < 4; k++) if (gp+k < HT) tmp[k] = inb[(size_t)c*HT + gp + k];
            v = make_float4(tmp[0],tmp[1],tmp[2],tmp[3]);
        }
        *(float4*)(sx + c*128 + j*4) = v;
    }
    __syncthreads();

    int p = px*4;
    float acc[32];
    #pragma unroll
    for (int i = 0; i < 32; i++) acc[i] = 0.f;

    #pragma unroll
    for (int c4 = 0; c4 < 16; c4++) {
        const float* xb = sx + c4*4*128 + p;
        float4 x0 = *(const float4*)(xb);
        float4 x1 = *(const float4*)(xb + 128);
        float4 x2 = *(const float4*)(xb + 256);
        float4 x3 = *(const float4*)(xb + 384);
        #pragma unroll
        for (int o8 = 0; o8 < 8; o8++) {
            float4 wv = *(const float4*)(sW + (oy*8 + o8)*64 + c4*4);
            float* a = acc + o8*4;
            a[0] = fmaf(wv.x, x0.x, a[0]); a[1] = fmaf(wv.x, x0.y, a[1]);
            a[2] = fmaf(wv.x, x0.z, a[2]); a[3] = fmaf(wv.x, x0.w, a[3]);
            a[0] = fmaf(wv.y, x1.x, a[0]); a[1] = fmaf(wv.y, x1.y, a[1]);
            a[2] = fmaf(wv.y, x1.z, a[2]); a[3] = fmaf(wv.y, x1.w, a[3]);
            a[0] = fmaf(wv.z, x2.x, a[0]); a[1] = fmaf(wv.z, x2.y, a[1]);
            a[2] = fmaf(wv.z, x2.z, a[2]); a[3] = fmaf(wv.z, x2.w, a[3]);
            a[0] = fmaf(wv.w, x3.x, a[0]); a[1] = fmaf(wv.w, x3.y, a[1]);
            a[2] = fmaf(wv.w, x3.z, a[2]); a[3] = fmaf(wv.w, x3.w, a[3]);
        }
    }

    // epilogue
    int gp0 = pos0 + p;
    bool full = (gp0 + 3) < HT;
    float* outb = out + (size_t)b*CC*HT;
    float psum[4] = {0,0,0,0};
    float pmax[4] = {-FLT_MAX,-FLT_MAX,-FLT_MAX,-FLT_MAX};
    #pragma unroll
    for (int o8 = 0; o8 < 8; o8++) {
        int o = oy*8 + o8;
        float r[4];
        #pragma unroll
        for (int k = 0; k < 4; k++) r[k] = acc[o8*4+k];
        if (gamma) {
            float g = __ldg(gamma + o), be = __ldg(beta + o);
            #pragma unroll
            for (int k = 0; k < 4; k++) r[k] = fmaf(r[k], g, be);
        }
        #pragma unroll
        for (int k = 0; k < 4; k++) {
            if (ACT == 1) r[k] = fmaxf(r[k], 0.f);
            if (ACT == 2) r[k] = 1.f/(1.f + expf(-r[k]));
        }
        if (SPSTATS) {
            #pragma unroll
            for (int k = 0; k < 4; k++) { psum[k] += r[k]; pmax[k] = fmaxf(pmax[k], r[k]); }
        }
        if (full) {
            *(float4*)(outb + (size_t)o*HT + gp0) = make_float4(r[0],r[1],r[2],r[3]);
        } else {
            for (int k = 0; k < 4; k++) if (gp0+k < HT) outb[(size_t)o*HT + gp0 + k] = r[k];
        }
    }

    if (SPSTATS) {
        #pragma unroll
        for (int k = 0; k < 4; k++) { sredS[oy*128 + p + k] = psum[k]; sredM[oy*128 + p + k] = pmax[k]; }
        __syncthreads();
        if (tid < 128) {
            float s = 0.f, m = -FLT_MAX;
            #pragma unroll
            for (int g = 0; g < 8; g++) { s += sredS[g*128 + tid]; m = fmaxf(m, sredM[g*128 + tid]); }
            int gp = pos0 + tid;
            if (gp < HT) {
                sp[(size_t)b*2*HT + gp]      = s*(1.f/CC);
                sp[(size_t)b*2*HT + HT + gp] = m;
            }
        }
    }
}

// ============ fused dw1x3(b1^2 * a_ch) + pointwise + bn + sigmoid ==========
// smem: region1 = sraw[64][132] (33792B) unioned with sW (16KB); sx @8448 floats.
__launch_bounds__(256)
__global__ void cb_fused(const float* __restrict__ b1, const float* __restrict__ ach,
                         const float* __restrict__ dw, const float* __restrict__ W,
                         const float* __restrict__ gamma, const float* __restrict__ beta,
                         float* __restrict__ out)
{
    extern __shared__ float sm[];
    float* sraw = sm;              // 64*132
    float* sW   = sm;              // union (after conv phase)
    float* sx   = sm + 8448;       // 64*128

    int tid = threadIdx.x;
    int px = tid & 31, oy = tid >> 5;
    int b = blockIdx.y;
    int pos0 = blockIdx.x * 128;
    const float* inb = b1 + (size_t)b*CC*HT;

    // phase A: f = v^2 * a into sraw (positions pos0-1 .. pos0+128)
    for (int i = tid; i < 64*130; i += 256) {
        int c = i / 130, j = i - c*130;
        int gp = pos0 - 1 + j;
        float v = 0.f;
        if (gp >= 0 && gp < HT) v = inb[(size_t)c*HT + gp];
        float a = __ldg(ach + b*CC + c);
        sraw[c*132 + j] = v*v*a;
    }
    __syncthreads();

    // phase B: 1x3 conv along t into sx
    for (int i = tid; i < 8192; i += 256) {
        int c = i >> 7, j = i & 127;
        int gp = pos0 + j;
        float r = 0.f;
        if (gp < HT) {
            int t = gp - (gp/TT)*TT;
            float w0 = __ldg(dw + c*3), w1 = __ldg(dw + c*3 + 1), w2 = __ldg(dw + c*3 + 2);
            r = w1 * sraw[c*132 + j + 1];
            if (t > 0)    r = fmaf(w0, sraw[c*132 + j],     r);
            if (t < TT-1) r = fmaf(w2, sraw[c*132 + j + 2], r);
        }
        sx[c*128 + j] = r;
    }
    __syncthreads();

    // phase C: load W (overwrites sraw region)
    #pragma unroll
    for (int i = tid; i < 1024; i += 256)
        ((float4*)sW)[i] = ((const float4*)W)[i];
    __syncthreads();

    // phase D: pw + bn + sigmoid
    int p = px*4;
    float acc[32];
    #pragma unroll
    for (int i = 0; i < 32; i++) acc[i] = 0.f;
    #pragma unroll
    for (int c4 = 0; c4 < 16; c4++) {
        const float* xb = sx + c4*4*128 + p;
        float4 x0 = *(const float4*)(xb);
        float4 x1 = *(const float4*)(xb + 128);
        float4 x2 = *(const float4*)(xb + 256);
        float4 x3 = *(const float4*)(xb + 384);
        #pragma unroll
        for (int o8 = 0; o8 < 8; o8++) {
            float4 wv = *(const float4*)(sW + (oy*8 + o8)*64 + c4*4);
            float* a = acc + o8*4;
            a[0] = fmaf(wv.x, x0.x, a[0]); a[1] = fmaf(wv.x, x0.y, a[1]);
            a[2] = fmaf(wv.x, x0.z, a[2]); a[3] = fmaf(wv.x, x0.w, a[3]);
            a[0] = fmaf(wv.y, x1.x, a[0]); a[1] = fmaf(wv.y, x1.y, a[1]);
            a[2] = fmaf(wv.y, x1.z, a[2]); a[3] = fmaf(wv.y, x1.w, a[3]);
            a[0] = fmaf(wv.z, x2.x, a[0]); a[1] = fmaf(wv.z, x2.y, a[1]);
            a[2] = fmaf(wv.z, x2.z, a[2]); a[3] = fmaf(wv.z, x2.w, a[3]);
            a[0] = fmaf(wv.w, x3.x, a[0]); a[1] = fmaf(wv.w, x3.y, a[1]);
            a[2] = fmaf(wv.w, x3.z, a[2]); a[3] = fmaf(wv.w, x3.w, a[3]);
        }
    }
    int gp0 = pos0 + p;
    bool full = (gp0 + 3) < HT;
    float* outb = out + (size_t)b*CC*HT;
    #pragma unroll
    for (int o8 = 0; o8 < 8; o8++) {
        int o = oy*8 + o8;
        float g = __ldg(gamma + o), be = __ldg(beta + o);
        float r[4];
        #pragma unroll
        for (int k = 0; k < 4; k++) {
            r[k] = fmaf(acc[o8*4+k], g, be);
            r[k] = 1.f/(1.f + expf(-r[k]));
        }
        if (full) *(float4*)(outb + (size_t)o*HT + gp0) = make_float4(r[0],r[1],r[2],r[3]);
        else for (int k = 0; k < 4; k++) if (gp0+k < HT) outb[(size_t)o*HT + gp0 + k] = r[k];
    }
}

// ---------------- dual depthwise 5x5 conv, pad 2, optional reversed-T read ------
__global__ void dw5_dual(const float* __restrict__ in, const float* __restrict__ w0,
                         const float* __restrict__ w1,
                         float* __restrict__ out0, float* __restrict__ out1, int rev)
{
    int bc = blockIdx.z;
    int c  = bc & (CC-1);
    __shared__ float tile[12][36];
    int t0 = blockIdx.x*32 - 2;
    int h0 = blockIdx.y*8  - 2;
    const float* base = in + (size_t)bc*HT;
    int tid = threadIdx.y*32 + threadIdx.x;
    for (int i = tid; i < 12*36; i += 256) {
        int hh = i / 36, tt = i % 36;
        int h = h0 + hh, t = t0 + tt;
        float v = 0.f;
        if (h >= 0 && h < HH && t >= 0 && t < TT) {
            int tr = rev ? (TT-1-t) : t;
            v = base[h*TT + tr];
        }
        tile[hh][tt] = v;
    }
    __syncthreads();
    int t = blockIdx.x*32 + threadIdx.x;
    int h = blockIdx.y*8  + threadIdx.y;
    if (t >= TT || h >= HH) return;
    const float* W0 = w0 + c*25;
    const float* W1 = w1 + c*25;
    float a0 = 0.f, a1 = 0.f;
    #pragma unroll
    for (int kh = 0; kh < 5; kh++)
        #pragma unroll
        for (int kw = 0; kw < 5; kw++) {
            float v = tile[threadIdx.y+kh][threadIdx.x+kw];
            a0 = fmaf(v, __ldg(&W0[kh*5+kw]), a0);
            a1 = fmaf(v, __ldg(&W1[kh*5+kw]), a1);
        }
    out0[(size_t)bc*HT + h*TT + t] = a0;
    out1[(size_t)bc*HT + h*TT + t] = a1;
}

// ---------------- channel attention stats -------------------------------------
__global__ void chan_stats(const float* __restrict__ in, float* __restrict__ avg,
                           float* __restrict__ mx)
{
    int bc = blockIdx.x;
    const float* p = in + (size_t)bc*HT;
    float s = 0.f, m = -FLT_MAX;
    for (int i = threadIdx.x; i < HT; i += 256) { float v = p[i]; s += v; m = fmaxf(m, v); }
    __shared__ float ssm[256], smm[256];
    ssm[threadIdx.x] = s; smm[threadIdx.x] = m;
    __syncthreads();
    for (int st = 128; st > 0; st >>= 1) {
        if (threadIdx.x < st) {
            ssm[threadIdx.x] += ssm[threadIdx.x+st];
            smm[threadIdx.x] = fmaxf(smm[threadIdx.x], smm[threadIdx.x+st]);
        }
        __syncthreads();
    }
    if (threadIdx.x == 0) { avg[bc] = ssm[0]/(float)HT; mx[bc] = smm[0]; }
}

// ---------------- channel attention MLP ---------------------------------------
__global__ void chan_attn(const float* __restrict__ avg, const float* __restrict__ mx,
                          const float* __restrict__ w1, const float* __restrict__ w2,
                          float* __restrict__ a)
{
    int b = blockIdx.x;
    int c = threadIdx.x;   // 64 threads
    __shared__ float sa[CC], sm[CC], hs[MIDC];
    sa[c] = avg[b*CC + c];
    sm[c] = mx[b*CC + c];
    __syncthreads();
    if (c < MIDC) {
        float ha = 0.f, hm = 0.f;
        for (int k = 0; k < CC; k++) {
            ha = fmaf(sa[k], w1[c*CC + k], ha);
            hm = fmaf(sm[k], w1[c*CC + k], hm);
        }
        hs[c] = fmaxf(ha, 0.f) + fmaxf(hm, 0.f);
    }
    __syncthreads();
    float acc = 0.f;
    #pragma unroll
    for (int j = 0; j < MIDC; j++) acc = fmaf(hs[j], w2[c*MIDC + j], acc);
    a[b*CC + c] = 1.f/(1.f + expf(-acc));
}

// ---------------- spatial attention 7x7 conv (2ch->1) + sigmoid -----------------
__global__ void spat_conv(const float* __restrict__ sp, const float* __restrict__ w,
                          float* __restrict__ asp)
{
    int t = blockIdx.x*32 + threadIdx.x;
    int h = blockIdx.y*8  + threadIdx.y;
    int b = blockIdx.z;
    if (t >= TT || h >= HH) return;
    float acc = 0.f;
    #pragma unroll
    for (int ci = 0; ci < 2; ci++) {
        const float* base = sp + ((size_t)b*2 + ci)*HT;
        #pragma unroll
        for (int kh = 0; kh < 7; kh++) {
            int hh = h + kh - 3;
            if (hh < 0 || hh >= HH) continue;
            #pragma unroll
            for (int kw = 0; kw < 7; kw++) {
                int tt = t + kw - 3;
                if (tt < 0 || tt >= TT) continue;
                acc = fmaf(base[hh*TT + tt], __ldg(&w[ci*49 + kh*7 + kw]), acc);
            }
        }
    }
    asp[(size_t)b*HT + h*TT + t] = 1.f/(1.f + expf(-acc));
}

// ---------------- SSM precompute: warp-shuffle recurrence, both halves ----------
__global__ void ssm_pre2(const float* __restrict__ A, const float* __restrict__ Bv,
                         const float* __restrict__ Cm, float* __restrict__ sc)
{
    int half = blockIdx.x;
    A  += half*SSZ*SSZ;
    Bv += half*SSZ;
    Cm += half*SSZ*CC;
    sc += half*TT*CC;
    int lid = threadIdx.x;  // 32 threads
    float Arow[SSZ], C0[SSZ], C1[SSZ];
    #pragma unroll
    for (int j = 0; j < SSZ; j++) Arow[j] = A[lid*SSZ + j];
    #pragma unroll
    for (int i = 0; i < SSZ; i++) { C0[i] = Cm[i*CC + lid]; C1[i] = Cm[i*CC + 32 + lid]; }
    float bv = Bv[lid];
    float st = 0.f;
    for (int t = 0; t < TT; t++) {
        float ns = bv;
        #pragma unroll
        for (int j = 0; j < SSZ; j++) ns = fmaf(__shfl_sync(0xffffffffu, st, j), Arow[j], ns);
        st = ns;
        float a0 = 0.f, a1 = 0.f;
        #pragma unroll
        for (int i = 0; i < SSZ; i++) {
            float s = __shfl_sync(0xffffffffu, st, i);
            a0 = fmaf(s, C0[i], a0);
            a1 = fmaf(s, C1[i], a1);
        }
        sc[t*CC + lid] = a0;
        sc[t*CC + 32 + lid] = a1;
    }
}

// ---------------- fused: residual-gelu + channel-LN + spatial gate --------------
// Raw-reshape scramble: scan-channel c2 = (h - 2c) & 63.
// Block: 256 = 32 pos x 8 channel-groups; 8 channels per thread in regs.
__launch_bounds__(256)
__global__ void final_fuse(const float* __restrict__ cb, const float* __restrict__ b2,
                           const float* __restrict__ asp, const float* __restrict__ sc,
                           const float* __restrict__ Dv, const float* __restrict__ lg,
                           const float* __restrict__ lb, float* __restrict__ out, int revout)
{
    __shared__ float sred[256];
    __shared__ float smu[32], srs[32];
    __shared__ float sD[CC], slg[CC], slb[CC];

    int tid = threadIdx.x;
    int px = tid & 31, cy = tid >> 5;
    int b = blockIdx.y;
    int pos = blockIdx.x*32 + px;      // HT = 775*32 exactly
    if (tid < CC) { sD[tid] = Dv[tid]; slg[tid] = lg[tid]; slb[tid] = lb[tid]; }
    __syncthreads();

    int t = pos % TT, h = pos / TT;
    const float* cbb = cb + (size_t)b*CC*HT + pos;
    const float* b2b = b2 + (size_t)b*CC*HT + pos;
    const float* scp = sc + t*CC;

    float val[8], bvv[8];
    float sum = 0.f;
    #pragma unroll
    for (int k = 0; k < 8; k++) {
        int c = cy*8 + k;
        int c2 = (h - 2*c) & (CC-1);
        float x = cbb[(size_t)c*HT];
        bvv[k] = b2b[(size_t)c*HT];
        float pre = __ldg(scp + c2) + x*sD[c2];
        float gel = 0.5f*pre*(1.f + erff(pre*0.70710678118654752f));
        val[k] = x + gel;
        sum += val[k];
    }
    sred[cy*32 + px] = sum;
    __syncthreads();
    if (cy == 0) {
        float tot = 0.f;
        #pragma unroll
        for (int g = 0; g < 8; g++) tot += sred[g*32 + px];
        smu[px] = tot*(1.f/CC);
    }
    __syncthreads();
    float mu = smu[px];
    float vp = 0.f;
    #pragma unroll
    for (int k = 0; k < 8; k++) { float d = val[k]-mu; vp = fmaf(d, d, vp); }
    __syncthreads();
    sred[cy*32 + px] = vp;
    __syncthreads();
    if (cy == 0) {
        float tot = 0.f;
        #pragma unroll
        for (int g = 0; g < 8; g++) tot += sred[g*32 + px];
        srs[px] = rsqrtf(tot*(1.f/CC) + 1e-5f);
    }
    __syncthreads();
    float rstd = srs[px];
    float aspv = asp[(size_t)b*HT + pos];
    int opos = revout ? (h*TT + (TT-1-t)) : pos;
    float* outb = out + (size_t)b*CC*HT + opos;
    #pragma unroll
    for (int k = 0; k < 8; k++) {
        int c = cy*8 + k;
        float y = (val[k]-mu)*rstd*slg[c] + slb[c];
        float sb = 1.f/(1.f + expf(-(bvv[k]*bvv[k]*aspv)));
        outb[(size_t)c*HT] = y*sb;
    }
}

// ---------------- host orchestration --------------------------------------------
#define PW_SMEM   49152
#define PWS_SMEM  57344
#define CB_SMEM   66560

static void run_half(const float* in, float* outb, int rev,
                     const float* dwdw, const float* dwpw, const float* dwg, const float* dwb,
                     const float* caw1, const float* caw2, const float* saw,
                     const float* d1dw, const float* d1pw, const float* d1g, const float* d1b,
                     const float* sD, const float* lng, const float* lnb,
                     const float* psc_half,
                     float* bufB, float* bufC, float* bufD,
                     float* pavg, float* pmx, float* pach, float* psp, float* pasp)
{
    dim3 g5((TT+31)/32, (HH+7)/8, BB*CC), b5(32, 8);
    dw5_dual<<<g5, b5>>>(in, dwdw, dwdw + CC*25, bufB, bufC, rev);

    dim3 gp((HT+127)/128, BB);
    pw2<1,false><<<gp, 256, PW_SMEM>>>(bufB, dwpw,       dwg,    dwb,    bufB, nullptr);  // b1
    pw2<1,true ><<<gp, 256, PWS_SMEM>>>(bufC, dwpw+CC*CC, dwg+CC, dwb+CC, bufC, psp);     // b2 + spat stats

    chan_stats<<<BB*CC, 256>>>(bufB, pavg, pmx);
    chan_attn<<<BB, 64>>>(pavg, pmx, caw1, caw2, pach);

    cb_fused<<<gp, 256, CB_SMEM>>>(bufB, pach, d1dw, d1pw, d1g, d1b, bufD);               // cb

    spat_conv<<<dim3((TT+31)/32, (HH+7)/8, BB), dim3(32, 8)>>>(psp, saw, pasp);

    final_fuse<<<dim3(HT/32, BB), 256>>>(bufD, bufC, pasp, psc_half, sD, lng, lnb, outb, rev);
}

extern "C" void kernel_launch(void* const* d_in, const int* in_sizes, int n_in,
                              void* d_out, int out_size)
{
    const float* x       = (const float*)d_in[0];
    const float* in_w    = (const float*)d_in[1];
    const float* dw2d_dw = (const float*)d_in[2];
    const float* dw2d_pw = (const float*)d_in[3];
    const float* dw2d_g  = (const float*)d_in[4];
    const float* dw2d_b  = (const float*)d_in[5];
    const float* ca_w1   = (const float*)d_in[6];
    const float* ca_w2   = (const float*)d_in[7];
    const float* sa_w    = (const float*)d_in[8];
    const float* dw1d_dw = (const float*)d_in[9];
    const float* dw1d_pw = (const float*)d_in[10];
    const float* dw1d_g  = (const float*)d_in[11];
    const float* dw1d_b  = (const float*)d_in[12];
    const float* ssm_A   = (const float*)d_in[13];
    const float* ssm_B   = (const float*)d_in[14];
    const float* ssm_C   = (const float*)d_in[15];
    const float* ssm_D   = (const float*)d_in[16];
    const float* ln_g    = (const float*)d_in[17];
    const float* ln_b    = (const float*)d_in[18];
    const float* out_w   = (const float*)d_in[19];
    const float* out_g   = (const float*)d_in[20];
    const float* out_b   = (const float*)d_in[21];

    float *pA, *pB, *pC, *pD, *pE, *pavg, *pmx, *pach, *psp, *pasp, *psc;
    cudaGetSymbolAddress((void**)&pA,   g_A);
    cudaGetSymbolAddress((void**)&pB,   g_B2);
    cudaGetSymbolAddress((void**)&pC,   g_C2);
    cudaGetSymbolAddress((void**)&pD,   g_D2);
    cudaGetSymbolAddress((void**)&pE,   g_E2);
    cudaGetSymbolAddress((void**)&pavg, g_avg);
    cudaGetSymbolAddress((void**)&pmx,  g_mxv);
    cudaGetSymbolAddress((void**)&pach, g_ach);
    cudaGetSymbolAddress((void**)&psp,  g_sp);
    cudaGetSymbolAddress((void**)&pasp, g_asp);
    cudaGetSymbolAddress((void**)&psc,  g_sc);

    cudaFuncSetAttribute(pw2<0,false>, cudaFuncAttributeMaxDynamicSharedMemorySize, PW_SMEM);
    cudaFuncSetAttribute(pw2<1,false>, cudaFuncAttributeMaxDynamicSharedMemorySize, PW_SMEM);
    cudaFuncSetAttribute(pw2<1,true>,  cudaFuncAttributeMaxDynamicSharedMemorySize, PWS_SMEM);
    cudaFuncSetAttribute(cb_fused,     cudaFuncAttributeMaxDynamicSharedMemorySize, CB_SMEM);

    // SSM tables for both halves (input-independent) — no dependencies, launch first
    ssm_pre2<<<2, 32>>>(ssm_A, ssm_B, ssm_C, psc);

    dim3 gp((HT+127)/128, BB);

    // input pointwise mix
    pw2<0,false><<<gp, 256, PW_SMEM>>>(x, in_w, nullptr, nullptr, pA, nullptr);

    // half 1 (normal orientation)
    run_half(pA, pE, 0,
             dw2d_dw, dw2d_pw, dw2d_g, dw2d_b,
             ca_w1, ca_w2, sa_w,
             dw1d_dw, dw1d_pw, dw1d_g, dw1d_b,
             ssm_D, ln_g, ln_b, psc,
             pB, pC, pD, pavg, pmx, pach, psp, pasp);

    // half 2 (reversed read, reversed write-back)
    run_half(pE, pA, 1,
             dw2d_dw + 2*CC*25, dw2d_pw + 2*CC*CC, dw2d_g + 2*CC, dw2d_b + 2*CC,
             ca_w1 + MIDC*CC, ca_w2 + CC*MIDC, sa_w + 2*49,
             dw1d_dw + CC*3, dw1d_pw + CC*CC, dw1d_g + CC, dw1d_b + CC,
             ssm_D + CC, ln_g + CC, ln_b + CC, psc + TT*CC,
             pB, pC, pD, pavg, pmx, pach, psp, pasp);

    // output pointwise mix + bn + relu
    pw2<1,false><<<gp, 256, PW_SMEM>>>(pA, out_w, out_g, out_b, (float*)d_out, nullptr);
}

// round 4
// speedup vs baseline: 2.1839x; 1.1402x over previous
#include <cuda_runtime.h>
#include <math.h>
#include <float.h>

#define BB 8
#define CC 64
#define HH 62
#define TT 400
#define HT (HH*TT)            // 24800
#define NTOT (BB*CC*HT)       // 12697600
#define SSZ 32
#define MIDC 4
#define NBLK 194              // ceil(HT/128)

// ---------------- scratch (device globals) ----------------
__device__ float g_A[NTOT];   // h / half2 output (un-reversed)
__device__ float g_B2[NTOT];  // b1
__device__ float g_C2[NTOT];  // b2
__device__ float g_D2[NTOT];  // cb
__device__ float g_E2[NTOT];  // half1 output
__device__ float g_ach[BB*CC];
__device__ float g_cps[BB*NBLK*CC];   // channel partial sums
__device__ float g_cpm[BB*NBLK*CC];   // channel partial maxes
__device__ float g_sp[BB*2*HT];
__device__ float g_asp[BB*HT];
__device__ float g_sc[2*TT*CC];

// ============ register-blocked pointwise 64x64 channel mix =================
// Block: 256 threads = 32 pos-groups (4 pos each) x 8 out-groups (8 outs each).
// Tile: 128 positions. smem: sW 16KB, sx 32KB, [spat stats 8KB].
// ACT: 0=none, 1=relu, 2=sigmoid. In-place safe.
// SPSTATS: emit per-position mean/max over channels (spatial attention input).
// CPARTS: emit per-channel partial sum/max over this block's positions.
template<int ACT, bool SPSTATS, bool CPARTS>
__launch_bounds__(256, 3)
__global__ void pw2(const float* __restrict__ in, const float* __restrict__ W,
                    const float* __restrict__ gamma, const float* __restrict__ beta,
                    float* __restrict__ out, float* __restrict__ sp,
                    float* __restrict__ cps, float* __restrict__ cpm)
{
    extern __shared__ float sm[];
    float* sW = sm;            // 4096 floats
    float* sx = sm + 4096;     // 64*128 floats
    float* sredS = sm + 4096 + 8192;   // 8*128 (SPSTATS)
    float* sredM = sredS + 1024;       // 8*128

    int tid = threadIdx.x;
    int px = tid & 31, oy = tid >> 5;
    int b = blockIdx.y;
    int pos0 = blockIdx.x * 128;
    const float* inb = in + (size_t)b*CC*HT;

    #pragma unroll
    for (int i = tid; i < 1024; i += 256)
        ((float4*)sW)[i] = ((const float4*)W)[i];

    #pragma unroll
    for (int i = tid; i < 2048; i += 256) {
        int c = i >> 5, j = i & 31;
        int gp = pos0 + j*4;
        float4 v = make_float4(0.f,0.f,0.f,0.f);
        if (gp + 3 < HT) {
            v = *(const float4*)(inb + (size_t)c*HT + gp);
        } else {
            float tmp[4] = {0,0,0,0};
            for (int k = 0; k < 4; k++) if (gp+k < HT) tmp[k] = inb[(size_t)c*HT + gp + k];
            v = make_float4(tmp[0],tmp[1],tmp[2],tmp[3]);
        }
        *(float4*)(sx + c*128 + j*4) = v;
    }
    __syncthreads();

    int p = px*4;
    float acc[32];
    #pragma unroll
    for (int i = 0; i < 32; i++) acc[i] = 0.f;

    #pragma unroll
    for (int c4 = 0; c4 < 16; c4++) {
        const float* xb = sx + c4*4*128 + p;
        float4 x0 = *(const float4*)(xb);
        float4 x1 = *(const float4*)(xb + 128);
        float4 x2 = *(const float4*)(xb + 256);
        float4 x3 = *(const float4*)(xb + 384);
        #pragma unroll
        for (int o8 = 0; o8 < 8; o8++) {
            float4 wv = *(const float4*)(sW + (oy*8 + o8)*64 + c4*4);
            float* a = acc + o8*4;
            a[0] = fmaf(wv.x, x0.x, a[0]); a[1] = fmaf(wv.x, x0.y, a[1]);
            a[2] = fmaf(wv.x, x0.z, a[2]); a[3] = fmaf(wv.x, x0.w, a[3]);
            a[0] = fmaf(wv.y, x1.x, a[0]); a[1] = fmaf(wv.y, x1.y, a[1]);
            a[2] = fmaf(wv.y, x1.z, a[2]); a[3] = fmaf(wv.y, x1.w, a[3]);
            a[0] = fmaf(wv.z, x2.x, a[0]); a[1] = fmaf(wv.z, x2.y, a[1]);
            a[2] = fmaf(wv.z, x2.z, a[2]); a[3] = fmaf(wv.z, x2.w, a[3]);
            a[0] = fmaf(wv.w, x3.x, a[0]); a[1] = fmaf(wv.w, x3.y, a[1]);
            a[2] = fmaf(wv.w, x3.z, a[2]); a[3] = fmaf(wv.w, x3.w, a[3]);
        }
    }

    int gp0 = pos0 + p;
    bool full = (gp0 + 3) < HT;
    float* outb = out + (size_t)b*CC*HT;
    float psum[4] = {0,0,0,0};
    float pmax[4] = {-FLT_MAX,-FLT_MAX,-FLT_MAX,-FLT_MAX};
    #pragma unroll
    for (int o8 = 0; o8 < 8; o8++) {
        int o = oy*8 + o8;
        float r[4];
        #pragma unroll
        for (int k = 0; k < 4; k++) r[k] = acc[o8*4+k];
        if (gamma) {
            float g = __ldg(gamma + o), be = __ldg(beta + o);
            #pragma unroll
            for (int k = 0; k < 4; k++) r[k] = fmaf(r[k], g, be);
        }
        #pragma unroll
        for (int k = 0; k < 4; k++) {
            if (ACT == 1) r[k] = fmaxf(r[k], 0.f);
            if (ACT == 2) r[k] = 1.f/(1.f + expf(-r[k]));
        }
        if (SPSTATS) {
            #pragma unroll
            for (int k = 0; k < 4; k++) { psum[k] += r[k]; pmax[k] = fmaxf(pmax[k], r[k]); }
        }
        if (CPARTS) {
            float ps = 0.f, pm = -FLT_MAX;
            #pragma unroll
            for (int k = 0; k < 4; k++) {
                if (gp0 + k < HT) { ps += r[k]; pm = fmaxf(pm, r[k]); }
            }
            #pragma unroll
            for (int s = 16; s > 0; s >>= 1) {
                ps += __shfl_xor_sync(0xffffffffu, ps, s);
                pm = fmaxf(pm, __shfl_xor_sync(0xffffffffu, pm, s));
            }
            if (px == 0) {
                cps[((size_t)b*NBLK + blockIdx.x)*CC + o] = ps;
                cpm[((size_t)b*NBLK + blockIdx.x)*CC + o] = pm;
            }
        }
        if (full) {
            *(float4*)(outb + (size_t)o*HT + gp0) = make_float4(r[0],r[1],r[2],r[3]);
        } else {
            for (int k = 0; k < 4; k++) if (gp0+k < HT) outb[(size_t)o*HT + gp0 + k] = r[k];
        }
    }

    if (SPSTATS) {
        #pragma unroll
        for (int k = 0; k < 4; k++) { sredS[oy*128 + p + k] = psum[k]; sredM[oy*128 + p + k] = pmax[k]; }
        __syncthreads();
        if (tid < 128) {
            float s = 0.f, m = -FLT_MAX;
            #pragma unroll
            for (int g = 0; g < 8; g++) { s += sredS[g*128 + tid]; m = fmaxf(m, sredM[g*128 + tid]); }
            int gp = pos0 + tid;
            if (gp < HT) {
                sp[(size_t)b*2*HT + gp]      = s*(1.f/CC);
                sp[(size_t)b*2*HT + HT + gp] = m;
            }
        }
    }
}

// ============ fused dw1x3(b1^2 * a_ch) + pointwise + bn + sigmoid ==========
__launch_bounds__(256, 3)
__global__ void cb_fused(const float* __restrict__ b1, const float* __restrict__ ach,
                         const float* __restrict__ dw, const float* __restrict__ W,
                         const float* __restrict__ gamma, const float* __restrict__ beta,
                         float* __restrict__ out)
{
    extern __shared__ float sm[];
    float* sraw = sm;              // 64*132
    float* sW   = sm;              // union (after conv phase)
    float* sx   = sm + 8448;       // 64*128

    int tid = threadIdx.x;
    int px = tid & 31, oy = tid >> 5;
    int b = blockIdx.y;
    int pos0 = blockIdx.x * 128;
    const float* inb = b1 + (size_t)b*CC*HT;

    for (int i = tid; i < 64*130; i += 256) {
        int c = i / 130, j = i - c*130;
        int gp = pos0 - 1 + j;
        float v = 0.f;
        if (gp >= 0 && gp < HT) v = inb[(size_t)c*HT + gp];
        float a = __ldg(ach + b*CC + c);
        sraw[c*132 + j] = v*v*a;
    }
    __syncthreads();

    for (int i = tid; i < 8192; i += 256) {
        int c = i >> 7, j = i & 127;
        int gp = pos0 + j;
        float r = 0.f;
        if (gp < HT) {
            int t = gp - (gp/TT)*TT;
            float w0 = __ldg(dw + c*3), w1 = __ldg(dw + c*3 + 1), w2 = __ldg(dw + c*3 + 2);
            r = w1 * sraw[c*132 + j + 1];
            if (t > 0)    r = fmaf(w0, sraw[c*132 + j],     r);
            if (t < TT-1) r = fmaf(w2, sraw[c*132 + j + 2], r);
        }
        sx[c*128 + j] = r;
    }
    __syncthreads();

    #pragma unroll
    for (int i = tid; i < 1024; i += 256)
        ((float4*)sW)[i] = ((const float4*)W)[i];
    __syncthreads();

    int p = px*4;
    float acc[32];
    #pragma unroll
    for (int i = 0; i < 32; i++) acc[i] = 0.f;
    #pragma unroll
    for (int c4 = 0; c4 < 16; c4++) {
        const float* xb = sx + c4*4*128 + p;
        float4 x0 = *(const float4*)(xb);
        float4 x1 = *(const float4*)(xb + 128);
        float4 x2 = *(const float4*)(xb + 256);
        float4 x3 = *(const float4*)(xb + 384);
        #pragma unroll
        for (int o8 = 0; o8 < 8; o8++) {
            float4 wv = *(const float4*)(sW + (oy*8 + o8)*64 + c4*4);
            float* a = acc + o8*4;
            a[0] = fmaf(wv.x, x0.x, a[0]); a[1] = fmaf(wv.x, x0.y, a[1]);
            a[2] = fmaf(wv.x, x0.z, a[2]); a[3] = fmaf(wv.x, x0.w, a[3]);
            a[0] = fmaf(wv.y, x1.x, a[0]); a[1] = fmaf(wv.y, x1.y, a[1]);
            a[2] = fmaf(wv.y, x1.z, a[2]); a[3] = fmaf(wv.y, x1.w, a[3]);
            a[0] = fmaf(wv.z, x2.x, a[0]); a[1] = fmaf(wv.z, x2.y, a[1]);
            a[2] = fmaf(wv.z, x2.z, a[2]); a[3] = fmaf(wv.z, x2.w, a[3]);
            a[0] = fmaf(wv.w, x3.x, a[0]); a[1] = fmaf(wv.w, x3.y, a[1]);
            a[2] = fmaf(wv.w, x3.z, a[2]); a[3] = fmaf(wv.w, x3.w, a[3]);
        }
    }
    int gp0 = pos0 + p;
    bool full = (gp0 + 3) < HT;
    float* outb = out + (size_t)b*CC*HT;
    #pragma unroll
    for (int o8 = 0; o8 < 8; o8++) {
        int o = oy*8 + o8;
        float g = __ldg(gamma + o), be = __ldg(beta + o);
        float r[4];
        #pragma unroll
        for (int k = 0; k < 4; k++) {
            r[k] = fmaf(acc[o8*4+k], g, be);
            r[k] = 1.f/(1.f + expf(-r[k]));
        }
        if (full) *(float4*)(outb + (size_t)o*HT + gp0) = make_float4(r[0],r[1],r[2],r[3]);
        else for (int k = 0; k < 4; k++) if (gp0+k < HT) outb[(size_t)o*HT + gp0 + k] = r[k];
    }
}

// ---------------- dual depthwise 5x5 conv, pad 2, optional reversed-T read ------
__global__ void dw5_dual(const float* __restrict__ in, const float* __restrict__ w0,
                         const float* __restrict__ w1,
                         float* __restrict__ out0, float* __restrict__ out1, int rev)
{
    int bc = blockIdx.z;
    int c  = bc & (CC-1);
    __shared__ float tile[12][36];
    int t0 = blockIdx.x*32 - 2;
    int h0 = blockIdx.y*8  - 2;
    const float* base = in + (size_t)bc*HT;
    int tid = threadIdx.y*32 + threadIdx.x;
    for (int i = tid; i < 12*36; i += 256) {
        int hh = i / 36, tt = i % 36;
        int h = h0 + hh, t = t0 + tt;
        float v = 0.f;
        if (h >= 0 && h < HH && t >= 0 && t < TT) {
            int tr = rev ? (TT-1-t) : t;
            v = base[h*TT + tr];
        }
        tile[hh][tt] = v;
    }
    __syncthreads();
    int t = blockIdx.x*32 + threadIdx.x;
    int h = blockIdx.y*8  + threadIdx.y;
    if (t >= TT || h >= HH) return;
    const float* W0 = w0 + c*25;
    const float* W1 = w1 + c*25;
    float a0 = 0.f, a1 = 0.f;
    #pragma unroll
    for (int kh = 0; kh < 5; kh++)
        #pragma unroll
        for (int kw = 0; kw < 5; kw++) {
            float v = tile[threadIdx.y+kh][threadIdx.x+kw];
            a0 = fmaf(v, __ldg(&W0[kh*5+kw]), a0);
            a1 = fmaf(v, __ldg(&W1[kh*5+kw]), a1);
        }
    out0[(size_t)bc*HT + h*TT + t] = a0;
    out1[(size_t)bc*HT + h*TT + t] = a1;
}

// ---------------- channel attention: reduce partials + MLP ---------------------
__global__ void chan_attn2(const float* __restrict__ cps, const float* __restrict__ cpm,
                           const float* __restrict__ w1, const float* __restrict__ w2,
                           float* __restrict__ a)
{
    int b = blockIdx.x, tid = threadIdx.x;   // 256 threads
    __shared__ float sa[CC], smx[CC], hs[MIDC];
    int c = tid >> 2, q = tid & 3;
    float s = 0.f, m = -FLT_MAX;
    for (int k = q; k < NBLK; k += 4) {
        s += cps[((size_t)b*NBLK + k)*CC + c];
        m = fmaxf(m, cpm[((size_t)b*NBLK + k)*CC + c]);
    }
    s += __shfl_xor_sync(0xffffffffu, s, 1);
    m = fmaxf(m, __shfl_xor_sync(0xffffffffu, m, 1));
    s += __shfl_xor_sync(0xffffffffu, s, 2);
    m = fmaxf(m, __shfl_xor_sync(0xffffffffu, m, 2));
    if (q == 0) { sa[c] = s*(1.f/(float)HT); smx[c] = m; }
    __syncthreads();
    if (tid < MIDC) {
        float ha = 0.f, hm = 0.f;
        for (int k = 0; k < CC; k++) {
            ha = fmaf(sa[k],  w1[tid*CC + k], ha);
            hm = fmaf(smx[k], w1[tid*CC + k], hm);
        }
        hs[tid] = fmaxf(ha, 0.f) + fmaxf(hm, 0.f);
    }
    __syncthreads();
    if (tid < CC) {
        float acc = 0.f;
        #pragma unroll
        for (int j = 0; j < MIDC; j++) acc = fmaf(hs[j], w2[tid*MIDC + j], acc);
        a[b*CC + tid] = 1.f/(1.f + expf(-acc));
    }
}

// ---------------- spatial attention 7x7 conv (2ch->1) + sigmoid -----------------
__global__ void spat_conv(const float* __restrict__ sp, const float* __restrict__ w,
                          float* __restrict__ asp)
{
    int t = blockIdx.x*32 + threadIdx.x;
    int h = blockIdx.y*8  + threadIdx.y;
    int b = blockIdx.z;
    if (t >= TT || h >= HH) return;
    float acc = 0.f;
    #pragma unroll
    for (int ci = 0; ci < 2; ci++) {
        const float* base = sp + ((size_t)b*2 + ci)*HT;
        #pragma unroll
        for (int kh = 0; kh < 7; kh++) {
            int hh = h + kh - 3;
            if (hh < 0 || hh >= HH) continue;
            #pragma unroll
            for (int kw = 0; kw < 7; kw++) {
                int tt = t + kw - 3;
                if (tt < 0 || tt >= TT) continue;
                acc = fmaf(base[hh*TT + tt], __ldg(&w[ci*49 + kh*7 + kw]), acc);
            }
        }
    }
    asp[(size_t)b*HT + h*TT + t] = 1.f/(1.f + expf(-acc));
}

// ---------------- SSM precompute: log-depth chain via A^8 ----------------------
// state(0)=B, state(t)=A*state(t-1)+B. 8 warps each step by A^8 (50 steps),
// states staged in smem, then parallel GEMM sc = S @ C.
// smem floats: sA@0(1024) sM@1024(1024) sT@2048(1024) sC@3072(2048) sVV@5120(32) sS@5152(12800)
#define SSM_SMEM ((5152 + TT*SSZ)*4)
__launch_bounds__(256)
__global__ void ssm_pre3(const float* __restrict__ A, const float* __restrict__ Bv,
                         const float* __restrict__ Cm, float* __restrict__ sc)
{
    extern __shared__ float sm[];
    float* sA  = sm;
    float* sM  = sm + 1024;
    float* sT  = sm + 2048;
    float* sC  = sm + 3072;
    float* sVV = sm + 5120;
    float* sS  = sm + 5152;

    int half = blockIdx.x;
    A  += half*SSZ*SSZ;
    Bv += half*SSZ;
    Cm += half*SSZ*CC;
    sc += (size_t)half*TT*CC;

    int tid = threadIdx.x;
    int wid = tid >> 5, lid = tid & 31;

    for (int i = tid; i < 1024; i += 256) sA[i] = A[i];
    for (int i = tid; i < 2048; i += 256) sC[i] = Cm[i];
    __syncthreads();
    // A2 -> sT
    for (int i = tid; i < 1024; i += 256) {
        int r = i >> 5, c = i & 31;
        float acc = 0.f;
        #pragma unroll
        for (int k = 0; k < 32; k++) acc = fmaf(sA[r*32+k], sA[k*32+c], acc);
        sT[i] = acc;
    }
    __syncthreads();
    // A4 -> sM
    for (int i = tid; i < 1024; i += 256) {
        int r = i >> 5, c = i & 31;
        float acc = 0.f;
        #pragma unroll
        for (int k = 0; k < 32; k++) acc = fmaf(sT[r*32+k], sT[k*32+c], acc);
        sM[i] = acc;
    }
    __syncthreads();
    // A8 -> sT
    for (int i = tid; i < 1024; i += 256) {
        int r = i >> 5, c = i & 31;
        float acc = 0.f;
        #pragma unroll
        for (int k = 0; k < 32; k++) acc = fmaf(sM[r*32+k], sM[k*32+c], acc);
        sT[i] = acc;
    }
    __syncthreads();

    // warp 0: first 8 states serially with A
    if (wid == 0) {
        float bv = Bv[lid];
        float Arow[32];
        #pragma unroll
        for (int j = 0; j < 32; j++) Arow[j] = sA[lid*32 + j];
        float x = bv;
        sS[lid] = x;
        #pragma unroll
        for (int k = 1; k < 8; k++) {
            float nx = bv;
            #pragma unroll
            for (int j = 0; j < 32; j++) nx = fmaf(__shfl_sync(0xffffffffu, x, j), Arow[j], nx);
            x = nx;
            sS[k*32 + lid] = x;
        }
        sVV[lid] = x;   // state(7) = (A^7+...+I)B
    }
    __syncthreads();

    // all 8 warps: x_{n+1} = A8 * x_n + vv, starting from state(wid)
    {
        float Mrow[32];
        #pragma unroll
        for (int j = 0; j < 32; j++) Mrow[j] = sT[lid*32 + j];
        float vv = sVV[lid];
        float x = sS[wid*32 + lid];
        for (int n = 1; n < 50; n++) {
            float p0 = vv, p1 = 0.f, p2 = 0.f, p3 = 0.f;
            #pragma unroll
            for (int j = 0; j < 8; j++) {
                p0 = fmaf(__shfl_sync(0xffffffffu, x, j),    Mrow[j],    p0);
                p1 = fmaf(__shfl_sync(0xffffffffu, x, j+8),  Mrow[j+8],  p1);
                p2 = fmaf(__shfl_sync(0xffffffffu, x, j+16), Mrow[j+16], p2);
                p3 = fmaf(__shfl_sync(0xffffffffu, x, j+24), Mrow[j+24], p3);
            }
            x = (p0 + p1) + (p2 + p3);
            sS[(wid + 8*n)*32 + lid] = x;
        }
    }
    __syncthreads();

    // parallel GEMM: sc[t][c] = sum_i S[t][i] * C[i][c]
    for (int i = tid; i < TT*CC; i += 256) {
        int t = i >> 6, c = i & 63;
        float acc = 0.f;
        #pragma unroll
        for (int k = 0; k < 32; k++) acc = fmaf(sS[t*32 + k], sC[k*64 + c], acc);
        sc[i] = acc;
    }
}

// ---------------- fused: residual-gelu + channel-LN + spatial gate --------------
// Raw-reshape scramble: scan-channel c2 = (h - 2c) & 63.
__launch_bounds__(256)
__global__ void final_fuse(const float* __restrict__ cb, const float* __restrict__ b2,
                           const float* __restrict__ asp, const float* __restrict__ sc,
                           const float* __restrict__ Dv, const float* __restrict__ lg,
                           const float* __restrict__ lb, float* __restrict__ out, int revout)
{
    __shared__ float sred[256];
    __shared__ float smu[32], srs[32];
    __shared__ float sD[CC], slg[CC], slb[CC];

    int tid = threadIdx.x;
    int px = tid & 31, cy = tid >> 5;
    int b = blockIdx.y;
    int pos = blockIdx.x*32 + px;      // HT = 775*32 exactly
    if (tid < CC) { sD[tid] = Dv[tid]; slg[tid] = lg[tid]; slb[tid] = lb[tid]; }
    __syncthreads();

    int t = pos % TT, h = pos / TT;
    const float* cbb = cb + (size_t)b*CC*HT + pos;
    const float* b2b = b2 + (size_t)b*CC*HT + pos;
    const float* scp = sc + t*CC;

    float val[8], bvv[8];
    float sum = 0.f;
    #pragma unroll
    for (int k = 0; k < 8; k++) {
        int c = cy*8 + k;
        int c2 = (h - 2*c) & (CC-1);
        float x = cbb[(size_t)c*HT];
        bvv[k] = b2b[(size_t)c*HT];
        float pre = __ldg(scp + c2) + x*sD[c2];
        float gel = 0.5f*pre*(1.f + erff(pre*0.70710678118654752f));
        val[k] = x + gel;
        sum += val[k];
    }
    sred[cy*32 + px] = sum;
    __syncthreads();
    if (cy == 0) {
        float tot = 0.f;
        #pragma unroll
        for (int g = 0; g < 8; g++) tot += sred[g*32 + px];
        smu[px] = tot*(1.f/CC);
    }
    __syncthreads();
    float mu = smu[px];
    float vp = 0.f;
    #pragma unroll
    for (int k = 0; k < 8; k++) { float d = val[k]-mu; vp = fmaf(d, d, vp); }
    __syncthreads();
    sred[cy*32 + px] = vp;
    __syncthreads();
    if (cy == 0) {
        float tot = 0.f;
        #pragma unroll
        for (int g = 0; g < 8; g++) tot += sred[g*32 + px];
        srs[px] = rsqrtf(tot*(1.f/CC) + 1e-5f);
    }
    __syncthreads();
    float rstd = srs[px];
    float aspv = asp[(size_t)b*HT + pos];
    int opos = revout ? (h*TT + (TT-1-t)) : pos;
    float* outb = out + (size_t)b*CC*HT + opos;
    #pragma unroll
    for (int k = 0; k < 8; k++) {
        int c = cy*8 + k;
        float y = (val[k]-mu)*rstd*slg[c] + slb[c];
        float sb = 1.f/(1.f + expf(-(bvv[k]*bvv[k]*aspv)));
        outb[(size_t)c*HT] = y*sb;
    }
}

// ---------------- host orchestration --------------------------------------------
#define PW_SMEM   49152
#define PWS_SMEM  57344
#define CB_SMEM   66560

static void run_half(const float* in, float* outb, int rev,
                     const float* dwdw, const float* dwpw, const float* dwg, const float* dwb,
                     const float* caw1, const float* caw2, const float* saw,
                     const float* d1dw, const float* d1pw, const float* d1g, const float* d1b,
                     const float* sD, const float* lng, const float* lnb,
                     const float* psc_half,
                     float* bufB, float* bufC, float* bufD,
                     float* pach, float* pcps, float* pcpm, float* psp, float* pasp)
{
    dim3 g5((TT+31)/32, (HH+7)/8, BB*CC), b5(32, 8);
    dw5_dual<<<g5, b5>>>(in, dwdw, dwdw + CC*25, bufB, bufC, rev);

    dim3 gp(NBLK, BB);
    pw2<1,false,true ><<<gp, 256, PW_SMEM>>>(bufB, dwpw,       dwg,    dwb,    bufB, nullptr, pcps, pcpm); // b1 + chan partials
    pw2<1,true ,false><<<gp, 256, PWS_SMEM>>>(bufC, dwpw+CC*CC, dwg+CC, dwb+CC, bufC, psp, nullptr, nullptr); // b2 + spat stats

    chan_attn2<<<BB, 256>>>(pcps, pcpm, caw1, caw2, pach);

    cb_fused<<<gp, 256, CB_SMEM>>>(bufB, pach, d1dw, d1pw, d1g, d1b, bufD);

    spat_conv<<<dim3((TT+31)/32, (HH+7)/8, BB), dim3(32, 8)>>>(psp, saw, pasp);

    final_fuse<<<dim3(HT/32, BB), 256>>>(bufD, bufC, pasp, psc_half, sD, lng, lnb, outb, rev);
}

extern "C" void kernel_launch(void* const* d_in, const int* in_sizes, int n_in,
                              void* d_out, int out_size)
{
    const float* x       = (const float*)d_in[0];
    const float* in_w    = (const float*)d_in[1];
    const float* dw2d_dw = (const float*)d_in[2];
    const float* dw2d_pw = (const float*)d_in[3];
    const float* dw2d_g  = (const float*)d_in[4];
    const float* dw2d_b  = (const float*)d_in[5];
    const float* ca_w1   = (const float*)d_in[6];
    const float* ca_w2   = (const float*)d_in[7];
    const float* sa_w    = (const float*)d_in[8];
    const float* dw1d_dw = (const float*)d_in[9];
    const float* dw1d_pw = (const float*)d_in[10];
    const float* dw1d_g  = (const float*)d_in[11];
    const float* dw1d_b  = (const float*)d_in[12];
    const float* ssm_A   = (const float*)d_in[13];
    const float* ssm_B   = (const float*)d_in[14];
    const float* ssm_C   = (const float*)d_in[15];
    const float* ssm_D   = (const float*)d_in[16];
    const float* ln_g    = (const float*)d_in[17];
    const float* ln_b    = (const float*)d_in[18];
    const float* out_w   = (const float*)d_in[19];
    const float* out_g   = (const float*)d_in[20];
    const float* out_b   = (const float*)d_in[21];

    float *pA, *pB, *pC, *pD, *pE, *pach, *pcps, *pcpm, *psp, *pasp, *psc;
    cudaGetSymbolAddress((void**)&pA,   g_A);
    cudaGetSymbolAddress((void**)&pB,   g_B2);
    cudaGetSymbolAddress((void**)&pC,   g_C2);
    cudaGetSymbolAddress((void**)&pD,   g_D2);
    cudaGetSymbolAddress((void**)&pE,   g_E2);
    cudaGetSymbolAddress((void**)&pach, g_ach);
    cudaGetSymbolAddress((void**)&pcps, g_cps);
    cudaGetSymbolAddress((void**)&pcpm, g_cpm);
    cudaGetSymbolAddress((void**)&psp,  g_sp);
    cudaGetSymbolAddress((void**)&pasp, g_asp);
    cudaGetSymbolAddress((void**)&psc,  g_sc);

    cudaFuncSetAttribute(pw2<0,false,false>, cudaFuncAttributeMaxDynamicSharedMemorySize, PW_SMEM);
    cudaFuncSetAttribute(pw2<1,false,false>, cudaFuncAttributeMaxDynamicSharedMemorySize, PW_SMEM);
    cudaFuncSetAttribute(pw2<1,false,true >, cudaFuncAttributeMaxDynamicSharedMemorySize, PW_SMEM);
    cudaFuncSetAttribute(pw2<1,true ,false>, cudaFuncAttributeMaxDynamicSharedMemorySize, PWS_SMEM);
    cudaFuncSetAttribute(cb_fused,           cudaFuncAttributeMaxDynamicSharedMemorySize, CB_SMEM);
    cudaFuncSetAttribute(ssm_pre3,           cudaFuncAttributeMaxDynamicSharedMemorySize, SSM_SMEM);

    // SSM tables for both halves (input-independent)
    ssm_pre3<<<2, 256, SSM_SMEM>>>(ssm_A, ssm_B, ssm_C, psc);

    dim3 gp(NBLK, BB);

    // input pointwise mix
    pw2<0,false,false><<<gp, 256, PW_SMEM>>>(x, in_w, nullptr, nullptr, pA, nullptr, nullptr, nullptr);

    // half 1 (normal orientation)
    run_half(pA, pE, 0,
             dw2d_dw, dw2d_pw, dw2d_g, dw2d_b,
             ca_w1, ca_w2, sa_w,
             dw1d_dw, dw1d_pw, dw1d_g, dw1d_b,
             ssm_D, ln_g, ln_b, psc,
             pB, pC, pD, pach, pcps, pcpm, psp, pasp);

    // half 2 (reversed read, reversed write-back)
    run_half(pE, pA, 1,
             dw2d_dw + 2*CC*25, dw2d_pw + 2*CC*CC, dw2d_g + 2*CC, dw2d_b + 2*CC,
             ca_w1 + MIDC*CC, ca_w2 + CC*MIDC, sa_w + 2*49,
             dw1d_dw + CC*3, dw1d_pw + CC*CC, dw1d_g + CC, dw1d_b + CC,
             ssm_D + CC, ln_g + CC, ln_b + CC, psc + TT*CC,
             pB, pC, pD, pach, pcps, pcpm, psp, pasp);

    // output pointwise mix + bn + relu
    pw2<1,false,false><<<gp, 256, PW_SMEM>>>(pA, out_w, out_g, out_b, (float*)d_out, nullptr, nullptr, nullptr);
}